// round 4
// baseline (speedup 1.0000x reference)
#include <cuda_runtime.h>

// 3x3 conv, stride 1, pad 1, single channel, X: (32, 1024, 1024) fp32.
// 4x4 register tile per thread; triple-buffered row prefetch (load row rr+2
// while computing row rr -> ~2-3 independent LDG.128 in flight per thread)
// plus early stores (output row flushed as soon as complete, freeing regs
// and interleaving write traffic with reads).
// Block = 256 threads covers 4 rows x 1024 cols. Grid = 32 * 256 = 8192.

#define IMG_W 1024
#define IMG_H 1024

__global__ __launch_bounds__(256, 5) void conv3x3_kernel(
    const float* __restrict__ X,
    const float* __restrict__ Wt,
    float* __restrict__ Y)
{
    const int tid   = threadIdx.x;
    const int bx    = blockIdx.x;
    const int batch = bx >> 8;        // / 256 row-groups
    const int rg    = bx & 255;
    const int r0    = rg << 2;        // first output row of this thread's tile
    const int c0    = tid << 2;       // first output col (float4 aligned)

    const size_t plane = (size_t)IMG_W * IMG_H;
    const float* Xb = X + (size_t)batch * plane;
    float*       Yb = Y + (size_t)batch * plane;

    float w[9];
#pragma unroll
    for (int i = 0; i < 9; i++) w[i] = __ldg(Wt + i);

    float acc[4][4];
#pragma unroll
    for (int i = 0; i < 4; i++)
#pragma unroll
        for (int j = 0; j < 4; j++) acc[i][j] = 0.0f;

    // Triple-buffered row registers: each buffer holds cols c0-1 .. c0+4.
    float rowbuf[3][6];

#define LOAD_ROW(s, r)                                                        \
    do {                                                                      \
        if ((r) >= 0 && (r) < IMG_H) {                                        \
            const float* p = Xb + (size_t)(r) * IMG_W + c0;                   \
            const float4 v = *reinterpret_cast<const float4*>(p);             \
            rowbuf[s][1] = v.x; rowbuf[s][2] = v.y;                           \
            rowbuf[s][3] = v.z; rowbuf[s][4] = v.w;                           \
            rowbuf[s][0] = (c0 > 0)         ? __ldg(p - 1) : 0.0f;            \
            rowbuf[s][5] = (c0 + 4 < IMG_W) ? __ldg(p + 4) : 0.0f;            \
        } else {                                                              \
            rowbuf[s][0] = 0.0f; rowbuf[s][1] = 0.0f; rowbuf[s][2] = 0.0f;    \
            rowbuf[s][3] = 0.0f; rowbuf[s][4] = 0.0f; rowbuf[s][5] = 0.0f;    \
        }                                                                     \
    } while (0)

    // Prime: rows r0-1 (slot 0) and r0 (slot 1).
    LOAD_ROW(0, r0 - 1);
    LOAD_ROW(1, r0);

    // Stream rows rr = -1 .. 4. Buffer for row (r0+rr) is slot (rr+1) mod 3.
    // At iteration rr we prefetch row rr+2 into slot (rr+3) mod 3 (free: its
    // previous occupant, row rr-1, was fully consumed at iteration rr-1).
#pragma unroll
    for (int rr = -1; rr <= 4; rr++) {
        const int cur = (rr + 1) % 3;
        if (rr <= 2) {
            LOAD_ROW((rr + 3) % 3, r0 + rr + 2);
        }

        // Output row i (0..3) uses input rows r0+i-1..r0+i+1 -> ky = rr-i+1.
#pragma unroll
        for (int i = 0; i < 4; i++) {
            const int ky = rr - i + 1;
            if (ky >= 0 && ky <= 2) {   // compile-time after unroll
#pragma unroll
                for (int j = 0; j < 4; j++) {
                    acc[i][j] = fmaf(w[ky * 3 + 0], rowbuf[cur][j],
                                fmaf(w[ky * 3 + 1], rowbuf[cur][j + 1],
                                fmaf(w[ky * 3 + 2], rowbuf[cur][j + 2],
                                     acc[i][j])));
                }
            }
        }

        // Output row (rr-1) received its final contribution (input row rr):
        // flush it now, freeing its accumulators.
        if (rr >= 1) {
            const int i = rr - 1;       // 0..3, compile-time after unroll
            float4 o;
            o.x = acc[i][0]; o.y = acc[i][1]; o.z = acc[i][2]; o.w = acc[i][3];
            *reinterpret_cast<float4*>(Yb + (size_t)(r0 + i) * IMG_W + c0) = o;
        }
    }
#undef LOAD_ROW
}

extern "C" void kernel_launch(void* const* d_in, const int* in_sizes, int n_in,
                              void* d_out, int out_size)
{
    const float* X  = (const float*)d_in[0];   // (32, 1024, 1024) fp32
    const float* Wt = (const float*)d_in[1];   // (3, 3) fp32
    float* Y        = (float*)d_out;           // (32, 1024, 1024) fp32

    const int grid = 32 * 256;                 // batches * 4-row groups
    conv3x3_kernel<<<grid, 256>>>(X, Wt, Y);
}